// round 14
// baseline (speedup 1.0000x reference)
#include <cuda_runtime.h>
#include <cuda_bf16.h>
#include <math.h>
#include <stdint.h>

#define Bb 32
#define Nn 512
#define Vv 5
#define Dd 256
#define Hh 4
#define BN (Bb*Nn)            // 16384 real nodes
#define Tt (BN + Bb*Vv)       // 16544 total nodes
#define TP 16640              // padded to 130*128 rows
#define Kk 256
#define NCHUNK 16

// ---------------- scratch ----------------------------------------------------
__device__ __nv_bfloat16 d_Ahi[(size_t)TP*Kk];
__device__ __nv_bfloat16 d_Alo[(size_t)TP*Kk];
__device__ __nv_bfloat16 d_WmHi[Dd*Kk];        // head-mean of gat_W, transposed
__device__ __nv_bfloat16 d_WmLo[Dd*Kk];
__device__ __nv_bfloat16 d_B2hi[Dd*Kk];        // gcn_W^T
__device__ __nv_bfloat16 d_B2lo[Dd*Kk];
__device__ float d_gatWt[1024*256];            // gat_W transposed [hc][k] fp32
__device__ float d_wsrc[Kk*Hh];                // [k][h]
__device__ float d_wdst[Kk*Hh];
__device__ float d_hmean[(size_t)TP*Dd];
__device__ float d_asrc[Hh*Tt];                // [head][t]
__device__ float d_adst[Hh*Tt];
__device__ float d_wself[128*Vv];              // self softmax weight [(b*4+h)*5+v]
__device__ float d_ypart[NCHUNK*Bb*20*Dd];
__device__ float d_gvirtH[Bb*Vv*Hh*Dd];        // [(bv)*4+h][c]
__device__ __nv_bfloat16 d_G1hi[(size_t)TP*Kk];
__device__ __nv_bfloat16 d_G1lo[(size_t)TP*Kk];
__device__ float d_xw[(size_t)TP*Dd];

// ---------------- helpers ----------------------------------------------------
__device__ __forceinline__ uint32_t smem_u32(const void* p) {
    uint32_t a;
    asm("{ .reg .u64 t; cvta.to.shared.u64 t, %1; cvt.u32.u64 %0, t; }"
        : "=r"(a) : "l"(p));
    return a;
}
__device__ __forceinline__ uint32_t sw64(uint32_t off) { return off ^ ((off >> 3) & 0x30); }

__device__ __forceinline__ void ldmx4(uint32_t* r, uint32_t addr) {
    asm volatile("ldmatrix.sync.aligned.m8n8.x4.shared.b16 {%0,%1,%2,%3}, [%4];"
                 : "=r"(r[0]), "=r"(r[1]), "=r"(r[2]), "=r"(r[3]) : "r"(addr));
}
__device__ __forceinline__ void mma16816(float* d, const uint32_t* a, uint32_t b0, uint32_t b1) {
    asm volatile(
        "mma.sync.aligned.m16n8k16.row.col.f32.bf16.bf16.f32 "
        "{%0,%1,%2,%3}, {%4,%5,%6,%7}, {%8,%9}, {%0,%1,%2,%3};"
        : "+f"(d[0]), "+f"(d[1]), "+f"(d[2]), "+f"(d[3])
        : "r"(a[0]), "r"(a[1]), "r"(a[2]), "r"(a[3]), "r"(b0), "r"(b1));
}
__device__ __forceinline__ void cp16(uint32_t smem_addr, const void* gptr) {
    asm volatile("cp.async.cg.shared.global [%0], [%1], 16;"
                 :: "r"(smem_addr), "l"(gptr));
}
__device__ __forceinline__ void cp_commit() {
    asm volatile("cp.async.commit_group;" ::: "memory");
}
__device__ __forceinline__ void cp_wait2() {
    asm volatile("cp.async.wait_group 2;" ::: "memory");
}
__device__ __forceinline__ void split_bf16(float v, __nv_bfloat16& hi, __nv_bfloat16& lo) {
    hi = __float2bfloat16(v);
    lo = __float2bfloat16(v - __bfloat162float(hi));
}
__device__ __forceinline__ uint32_t pack2(__nv_bfloat16 a, __nv_bfloat16 b) {
    return (uint32_t)__bfloat16_as_ushort(a) | ((uint32_t)__bfloat16_as_ushort(b) << 16);
}
__device__ __forceinline__ float warp_sum(float s) {
#pragma unroll
    for (int o = 16; o; o >>= 1) s += __shfl_xor_sync(0xffffffffu, s, o);
    return s;
}
__device__ __forceinline__ float lrelu(float x) { return x > 0.f ? x : 0.2f * x; }

// ---------------- fused prep (incl. gat_W transpose) -------------------------
__global__ void k_prep(const float* __restrict__ gat_W,
                       const float* __restrict__ att_src, const float* __restrict__ att_dst,
                       const float* __restrict__ gcn_W) {
    int bid = blockIdx.x;
    int tid = threadIdx.x;
    if (bid < 256) {
        int gw = bid * 8 + (tid >> 5);
        int lane = tid & 31;
        int k = gw >> 3;
        int h = (gw >> 1) & 3;
        bool is_dst = gw & 1;
        const float* wp = gat_W + (size_t)k * 1024 + h * 256;
        const float* ap = (is_dst ? att_dst : att_src) + h * 256;
        float s = 0.f;
#pragma unroll
        for (int j = 0; j < 8; j++) s += wp[lane + 32 * j] * ap[lane + 32 * j];
        s = warp_sum(s);
        if (lane == 0) {
            if (is_dst) d_wdst[k * 4 + h] = s;
            else        d_wsrc[k * 4 + h] = s;
        }
    } else if (bid < 512) {
        int n = bid - 256;
        int k = tid;
        const float* p = gat_W + (size_t)k * 1024 + n;
        float v = 0.25f * (p[0] + p[256] + p[512] + p[768]);
        __nv_bfloat16 hi, lo;
        split_bf16(v, hi, lo);
        d_WmHi[n * 256 + k] = hi;
        d_WmLo[n * 256 + k] = lo;
    } else if (bid < 768) {
        int idx = (bid - 512) * 256 + tid;
        int n = idx >> 8;
        int k = idx & 255;
        float v = gcn_W[k * 256 + n];
        __nv_bfloat16 hi, lo;
        split_bf16(v, hi, lo);
        d_B2hi[idx] = hi;
        d_B2lo[idx] = lo;
    } else {
        // 32x32-tiled transpose: gat_W [256 k][1024 hc] -> d_gatWt [1024 hc][256 k]
        __shared__ float tile[32][33];
        int tix = bid - 768;          // 0..255
        int kt = tix & 7;             // 8 k-tiles
        int ct = tix >> 3;            // 32 hc-tiles
        int row = tid >> 3;           // 0..31
        int col4 = (tid & 7) * 4;     // 0..28
#pragma unroll
        for (int j = 0; j < 4; j++)
            tile[row][col4 + j] = gat_W[(size_t)(kt * 32 + row) * 1024 + ct * 32 + col4 + j];
        __syncthreads();
#pragma unroll
        for (int j = 0; j < 4; j++)
            d_gatWt[(size_t)(ct * 32 + row) * 256 + kt * 32 + col4 + j] = tile[col4 + j][row];
    }
}

// ---------------- build: warp-per-node, vectorized, fused scores --------------
// (no more d_allf write — yagg reconstructs hi+lo)
__global__ void __launch_bounds__(256) k_build(const float* __restrict__ x,
                                               const float* __restrict__ vn) {
    __shared__ float ws[8][256];
    int tid = threadIdx.x;
#pragma unroll
    for (int i = 0; i < 8; i++) {
        int idx = tid + i * 256;
        int r = idx >> 8, k = idx & 255;
        ws[r][k] = (r < 4) ? d_wsrc[k * 4 + r] : d_wdst[k * 4 + (r & 3)];
    }
    __syncthreads();

    int w = tid >> 5, lane = tid & 31;
    int t = blockIdx.x * 8 + w;
    const float* src = (t < BN) ? (x + (size_t)t * Dd)
                                : (vn + (size_t)((t - BN) % Vv) * Dd);
    float4 f0 = *reinterpret_cast<const float4*>(src + 4 * lane);
    float4 f1 = *reinterpret_cast<const float4*>(src + 128 + 4 * lane);

    __nv_bfloat16 h[8], l[8];
    split_bf16(f0.x, h[0], l[0]); split_bf16(f0.y, h[1], l[1]);
    split_bf16(f0.z, h[2], l[2]); split_bf16(f0.w, h[3], l[3]);
    split_bf16(f1.x, h[4], l[4]); split_bf16(f1.y, h[5], l[5]);
    split_bf16(f1.z, h[6], l[6]); split_bf16(f1.w, h[7], l[7]);
    uint2* Ahi2 = reinterpret_cast<uint2*>(d_Ahi + (size_t)t * Dd);
    uint2* Alo2 = reinterpret_cast<uint2*>(d_Alo + (size_t)t * Dd);
    Ahi2[lane]      = make_uint2(pack2(h[0], h[1]), pack2(h[2], h[3]));
    Ahi2[lane + 32] = make_uint2(pack2(h[4], h[5]), pack2(h[6], h[7]));
    Alo2[lane]      = make_uint2(pack2(l[0], l[1]), pack2(l[2], l[3]));
    Alo2[lane + 32] = make_uint2(pack2(l[4], l[5]), pack2(l[6], l[7]));

    float s[8];
#pragma unroll
    for (int r = 0; r < 8; r++) {
        const float4* wr = reinterpret_cast<const float4*>(ws[r]);
        float4 w0 = wr[lane], w1 = wr[lane + 32];
        s[r] = f0.x * w0.x + f0.y * w0.y + f0.z * w0.z + f0.w * w0.w
             + f1.x * w1.x + f1.y * w1.y + f1.z * w1.z + f1.w * w1.w;
    }
#pragma unroll
    for (int o = 16; o; o >>= 1)
#pragma unroll
        for (int r = 0; r < 8; r++) s[r] += __shfl_xor_sync(0xffffffffu, s[r], o);

    if (lane < 4)      d_asrc[lane * Tt + t] = s[lane];
    else if (lane < 8) d_adst[(lane - 4) * Tt + t] = s[lane];
}

// ---------------- pipelined mma.sync split-bf16 GEMM (R7/R10 config) ---------
#define NSTAGE 4
#define STAGE_BYTES 32768
#define OFF_AH 0
#define OFF_AL 8192
#define OFF_BH 16384
#define OFF_BL 24576

__global__ void __launch_bounds__(256) k_mma_gemm(
    const __nv_bfloat16* __restrict__ Ahi, const __nv_bfloat16* __restrict__ Alo,
    const __nv_bfloat16* __restrict__ Bhi, const __nv_bfloat16* __restrict__ Blo,
    float* __restrict__ C)
{
    extern __shared__ __align__(128) char smem[];
    const uint32_t sbase = smem_u32(smem);

    const int tid = threadIdx.x;
    const int wid = tid >> 5, lane = tid & 31;
    const int wm = (wid >> 2) * 64;
    const int wn = (wid & 3) * 32;
    const int mBase = blockIdx.y * 128;
    const int nBase = blockIdx.x * 128;

    const int lrow0 = tid >> 2;
    const int lc16  = tid & 3;
    const uint4* A4h = reinterpret_cast<const uint4*>(Ahi);
    const uint4* A4l = reinterpret_cast<const uint4*>(Alo);
    const uint4* B4h = reinterpret_cast<const uint4*>(Bhi);
    const uint4* B4l = reinterpret_cast<const uint4*>(Blo);

    float acc[4][4][4];
#pragma unroll
    for (int i = 0; i < 4; i++)
#pragma unroll
        for (int j = 0; j < 4; j++)
#pragma unroll
            for (int e = 0; e < 4; e++) acc[i][j][e] = 0.f;

    const uint32_t aRow = (uint32_t)((lane & 7) + (lane & 8));
    const uint32_t aColB = (lane & 16) ? 16u : 0u;
    const uint32_t bRow = (uint32_t)((lane & 7) + ((lane & 16) >> 1));
    const uint32_t bColB = (lane & 8) ? 16u : 0u;

    auto prefetch = [&](int kc) {
        uint32_t st = sbase + (kc & (NSTAGE - 1)) * STAGE_BYTES;
#pragma unroll
        for (int q = 0; q < 2; q++) {
            int row = lrow0 + q * 64;
            uint32_t sw = sw64((uint32_t)(row * 64 + lc16 * 16));
            int ga = (mBase + row) * 32 + kc * 4 + lc16;
            int gb = (nBase + row) * 32 + kc * 4 + lc16;
            cp16(st + OFF_AH + sw, A4h + ga);
            cp16(st + OFF_AL + sw, A4l + ga);
            cp16(st + OFF_BH + sw, B4h + gb);
            cp16(st + OFF_BL + sw, B4l + gb);
        }
    };

    prefetch(0); cp_commit();
    prefetch(1); cp_commit();
    prefetch(2); cp_commit();

    for (int kc = 0; kc < 8; kc++) {
        cp_wait2();
        __syncthreads();
        if (kc + 3 < 8) prefetch(kc + 3);
        cp_commit();

        uint32_t st = sbase + (kc & (NSTAGE - 1)) * STAGE_BYTES;
#pragma unroll
        for (int s = 0; s < 2; s++) {
            uint32_t bh[2][4], bl[2][4];
#pragma unroll
            for (int ng = 0; ng < 2; ng++) {
                uint32_t byteo = sw64((uint32_t)((wn + ng * 16 + bRow) * 64) + s * 32u + bColB);
                ldmx4(bh[ng], st + OFF_BH + byteo);
                ldmx4(bl[ng], st + OFF_BL + byteo);
            }
#pragma unroll
            for (int mt = 0; mt < 4; mt++) {
                uint32_t ah[4], al[4];
                uint32_t byteo = sw64((uint32_t)((wm + mt * 16 + aRow) * 64) + s * 32u + aColB);
                ldmx4(ah, st + OFF_AH + byteo);
                ldmx4(al, st + OFF_AL + byteo);
#pragma unroll
                for (int ng = 0; ng < 2; ng++) {
                    mma16816(acc[mt][ng * 2],     ah, bh[ng][0], bh[ng][1]);
                    mma16816(acc[mt][ng * 2 + 1], ah, bh[ng][2], bh[ng][3]);
                    mma16816(acc[mt][ng * 2],     ah, bl[ng][0], bl[ng][1]);
                    mma16816(acc[mt][ng * 2 + 1], ah, bl[ng][2], bl[ng][3]);
                    mma16816(acc[mt][ng * 2],     al, bh[ng][0], bh[ng][1]);
                    mma16816(acc[mt][ng * 2 + 1], al, bh[ng][2], bh[ng][3]);
                }
            }
        }
    }

    int mThr = mBase + wm + (lane >> 2);
    int nThr = nBase + wn + (lane & 3) * 2;
#pragma unroll
    for (int mt = 0; mt < 4; mt++)
#pragma unroll
        for (int nt = 0; nt < 4; nt++) {
            int r0 = mThr + mt * 16;
            int cc = nThr + nt * 8;
            float2 v0 = make_float2(acc[mt][nt][0], acc[mt][nt][1]);
            float2 v1 = make_float2(acc[mt][nt][2], acc[mt][nt][3]);
            *reinterpret_cast<float2*>(C + (size_t)r0 * 256 + cc) = v0;
            *reinterpret_cast<float2*>(C + (size_t)(r0 + 8) * 256 + cc) = v1;
        }
}

// ---------------- fused softmax-weight + weighted-x aggregation ---------------
// grid 512: lb = b*16 + chunk. Standalone (small smem -> full occupancy).
// Softmax params recomputed per block by warps (validated in R11).
__global__ void __launch_bounds__(256) k_vwagg(const float* __restrict__ vn) {
    int lb = blockIdx.x;
    int b = lb >> 4, chunk = lb & 15;
    int tid = threadIdx.x;

    __shared__ float asrc_sh[4][Nn];
    __shared__ float st_m[20], st_inv[20], st_adst[20];
    __shared__ float w_sh[20][32];

    for (int i = tid; i < 4 * Nn; i += 256) {
        int h = i >> 9, k = i & 511;
        asrc_sh[h][k] = d_asrc[h * Tt + b * Nn + k];
    }
    __syncthreads();

    int w = tid >> 5, lane = tid & 31;
    for (int j = w; j < 20; j += 8) {      // j = v*4 + h
        int v = j >> 2, h = j & 3;
        int vt = BN + b * Vv + v;
        float adst = d_adst[h * Tt + vt];
        float aself = lrelu(d_asrc[h * Tt + vt] + adst);
        float mx = aself;
        for (int i = lane; i < Nn; i += 32)
            mx = fmaxf(mx, lrelu(asrc_sh[h][i] + adst));
#pragma unroll
        for (int o = 16; o; o >>= 1) mx = fmaxf(mx, __shfl_xor_sync(0xffffffffu, mx, o));
        float se = (lane == 0) ? expf(aself - mx) : 0.f;
        for (int i = lane; i < Nn; i += 32)
            se += expf(lrelu(asrc_sh[h][i] + adst) - mx);
        se = warp_sum(se);
        float inv = 1.f / se;
        if (lane == 0) {
            st_m[j] = mx; st_inv[j] = inv; st_adst[j] = adst;
            d_wself[(b * 4 + h) * Vv + v] = expf(aself - mx) * inv;  // dup writes, same value
        }
    }
    __syncthreads();

    for (int idx = tid; idx < 20 * 32; idx += 256) {
        int j = idx >> 5, ii = idx & 31;
        int h = j & 3;
        float a = lrelu(asrc_sh[h][chunk * 32 + ii] + st_adst[j]);
        w_sh[j][ii] = expf(a - st_m[j]) * st_inv[j];
    }
    __syncthreads();

    float acc[20];
#pragma unroll
    for (int j = 0; j < 20; j++) acc[j] = 0.f;
    int c = tid;
    size_t base = (size_t)(b * Nn + chunk * 32) * Dd + c;
    for (int ii = 0; ii < 32; ii++) {
        size_t idx = base + (size_t)ii * Dd;
        float xv = __bfloat162float(d_Ahi[idx]) + __bfloat162float(d_Alo[idx]);
#pragma unroll
        for (int j = 0; j < 20; j++) acc[j] += w_sh[j][ii] * xv;
    }
#pragma unroll
    for (int j = 0; j < 20; j++)
        d_ypart[(size_t)((chunk * Bb + b) * 20 + j) * Dd + c] = acc[j];
}

// ---------------- y-finalize + virtual GEMM (transposed weights) -------------
__global__ void __launch_bounds__(256) k_yv(const float* __restrict__ vn) {
    int g = blockIdx.x;
    int b = g >> 2, h = g & 3;
    int c = threadIdx.x;

    __shared__ float y[Vv][256];
#pragma unroll
    for (int v = 0; v < Vv; v++) {
        float s = 0.f;
        int vh = v * 4 + h;
#pragma unroll
        for (int chunk = 0; chunk < NCHUNK; chunk++)
            s += d_ypart[(size_t)((chunk * Bb + b) * 20 + vh) * Dd + c];
        s += d_wself[(b * 4 + h) * Vv + v] * vn[v * Dd + c];
        y[v][c] = s;
    }
    __syncthreads();

    float acc[Vv] = {0.f, 0.f, 0.f, 0.f, 0.f};
    const float4* wrow = reinterpret_cast<const float4*>(d_gatWt + (size_t)(h * 256 + c) * 256);
#pragma unroll 8
    for (int k4 = 0; k4 < 64; k4++) {
        float4 wv = wrow[k4];
        int k = k4 * 4;
#pragma unroll
        for (int v = 0; v < Vv; v++)
            acc[v] += y[v][k] * wv.x + y[v][k + 1] * wv.y
                    + y[v][k + 2] * wv.z + y[v][k + 3] * wv.w;
    }
#pragma unroll
    for (int v = 0; v < Vv; v++)
        d_gvirtH[(size_t)(((b * Vv + v) * 4) + h) * Dd + c] = acc[v];
}

// ---------------- gelu + layernorm (warp-per-node) ---------------------------
__device__ __forceinline__ float gelu_exact(float x) {
    return 0.5f * x * (1.f + erff(x * 0.70710678118654752f));
}

__global__ void __launch_bounds__(256) k_norm1(const float* __restrict__ gat_bias,
                                               const float* __restrict__ g,
                                               const float* __restrict__ bta) {
    int tid = threadIdx.x;
    int w = tid >> 5, lane = tid & 31;
    int t = blockIdx.x * 8 + w;

    float v[8];
    if (t < BN) {
        const float4* hp = reinterpret_cast<const float4*>(d_hmean + (size_t)t * Dd);
        float4 a = hp[lane], bq = hp[lane + 32];
        v[0]=a.x; v[1]=a.y; v[2]=a.z; v[3]=a.w;
        v[4]=bq.x; v[5]=bq.y; v[6]=bq.z; v[7]=bq.w;
    } else {
        size_t base = (size_t)(t - BN) * 4 * Dd;
        float4 s0 = make_float4(0,0,0,0), s1 = make_float4(0,0,0,0);
#pragma unroll
        for (int h = 0; h < 4; h++) {
            const float4* gp = reinterpret_cast<const float4*>(d_gvirtH + base + h * Dd);
            float4 a = gp[lane], bq = gp[lane + 32];
            s0.x += a.x; s0.y += a.y; s0.z += a.z; s0.w += a.w;
            s1.x += bq.x; s1.y += bq.y; s1.z += bq.z; s1.w += bq.w;
        }
        v[0]=0.25f*s0.x; v[1]=0.25f*s0.y; v[2]=0.25f*s0.z; v[3]=0.25f*s0.w;
        v[4]=0.25f*s1.x; v[5]=0.25f*s1.y; v[6]=0.25f*s1.z; v[7]=0.25f*s1.w;
    }
    const float4* bi = reinterpret_cast<const float4*>(gat_bias);
    float4 b0 = bi[lane], b1 = bi[lane + 32];
    v[0]+=b0.x; v[1]+=b0.y; v[2]+=b0.z; v[3]+=b0.w;
    v[4]+=b1.x; v[5]+=b1.y; v[6]+=b1.z; v[7]+=b1.w;

    float ge[8], s = 0.f;
#pragma unroll
    for (int i = 0; i < 8; i++) { ge[i] = gelu_exact(v[i]); s += ge[i]; }
    float mean = warp_sum(s) * (1.f / Dd);
    float sq = 0.f;
#pragma unroll
    for (int i = 0; i < 8; i++) { ge[i] -= mean; sq += ge[i] * ge[i]; }
    float rstd = rsqrtf(warp_sum(sq) * (1.f / Dd) + 1e-5f);

    const float4* gg = reinterpret_cast<const float4*>(g);
    const float4* gb = reinterpret_cast<const float4*>(bta);
    float4 g0 = gg[lane], g1 = gg[lane + 32];
    float4 t0 = gb[lane], t1 = gb[lane + 32];
    float o[8];
    o[0]=ge[0]*rstd*g0.x+t0.x; o[1]=ge[1]*rstd*g0.y+t0.y;
    o[2]=ge[2]*rstd*g0.z+t0.z; o[3]=ge[3]*rstd*g0.w+t0.w;
    o[4]=ge[4]*rstd*g1.x+t1.x; o[5]=ge[5]*rstd*g1.y+t1.y;
    o[6]=ge[6]*rstd*g1.z+t1.z; o[7]=ge[7]*rstd*g1.w+t1.w;

    __nv_bfloat16 h[8], l[8];
#pragma unroll
    for (int i = 0; i < 8; i++) split_bf16(o[i], h[i], l[i]);
    uint2* Ghi2 = reinterpret_cast<uint2*>(d_G1hi + (size_t)t * Dd);
    uint2* Glo2 = reinterpret_cast<uint2*>(d_G1lo + (size_t)t * Dd);
    Ghi2[lane]      = make_uint2(pack2(h[0], h[1]), pack2(h[2], h[3]));
    Ghi2[lane + 32] = make_uint2(pack2(h[4], h[5]), pack2(h[6], h[7]));
    Glo2[lane]      = make_uint2(pack2(l[0], l[1]), pack2(l[2], l[3]));
    Glo2[lane + 32] = make_uint2(pack2(l[4], l[5]), pack2(l[6], l[7]));
}

// final: warp per node, 8 nodes/block. grid BN/8. vsum fused (L2-resident rows).
__global__ void __launch_bounds__(256) k_final(const float* __restrict__ gcn_bias,
                                               const float* __restrict__ g,
                                               const float* __restrict__ bta,
                                               float* __restrict__ out) {
    int tid = threadIdx.x;
    int w = tid >> 5, lane = tid & 31;
    int t = blockIdx.x * 8 + w;
    int b = t >> 9;
    const float inv_sqrt6 = 0.40824829046386301637f;
    const float inv6 = 0.16666666666666666667f;

    // S[b] = sum_v xw[BN + b*5+v]  (5 virtual rows, shared by whole batch -> L2)
    float4 S0 = make_float4(0,0,0,0), S1 = make_float4(0,0,0,0);
#pragma unroll
    for (int v = 0; v < Vv; v++) {
        const float4* vp = reinterpret_cast<const float4*>(d_xw + (size_t)(BN + b * Vv + v) * Dd);
        float4 a = vp[lane], bq = vp[lane + 32];
        S0.x += a.x; S0.y += a.y; S0.z += a.z; S0.w += a.w;
        S1.x += bq.x; S1.y += bq.y; S1.z += bq.z; S1.w += bq.w;
    }

    const float4* xp = reinterpret_cast<const float4*>(d_xw + (size_t)t * Dd);
    const float4* bi = reinterpret_cast<const float4*>(gcn_bias);
    float4 x0 = xp[lane], x1 = xp[lane + 32];
    float4 b0 = bi[lane], b1 = bi[lane + 32];

    float v[8];
    v[0]=inv_sqrt6*S0.x+inv6*x0.x+b0.x; v[1]=inv_sqrt6*S0.y+inv6*x0.y+b0.y;
    v[2]=inv_sqrt6*S0.z+inv6*x0.z+b0.z; v[3]=inv_sqrt6*S0.w+inv6*x0.w+b0.w;
    v[4]=inv_sqrt6*S1.x+inv6*x1.x+b1.x; v[5]=inv_sqrt6*S1.y+inv6*x1.y+b1.y;
    v[6]=inv_sqrt6*S1.z+inv6*x1.z+b1.z; v[7]=inv_sqrt6*S1.w+inv6*x1.w+b1.w;

    float ge[8], s = 0.f;
#pragma unroll
    for (int i = 0; i < 8; i++) { ge[i] = gelu_exact(v[i]); s += ge[i]; }
    float mean = warp_sum(s) * (1.f / Dd);
    float sq = 0.f;
#pragma unroll
    for (int i = 0; i < 8; i++) { ge[i] -= mean; sq += ge[i] * ge[i]; }
    float rstd = rsqrtf(warp_sum(sq) * (1.f / Dd) + 1e-5f);

    const float4* gg = reinterpret_cast<const float4*>(g);
    const float4* gb = reinterpret_cast<const float4*>(bta);
    float4 g0 = gg[lane], g1 = gg[lane + 32];
    float4 t0 = gb[lane], t1 = gb[lane + 32];
    float4 o0 = make_float4(ge[0]*rstd*g0.x+t0.x, ge[1]*rstd*g0.y+t0.y,
                            ge[2]*rstd*g0.z+t0.z, ge[3]*rstd*g0.w+t0.w);
    float4 o1 = make_float4(ge[4]*rstd*g1.x+t1.x, ge[5]*rstd*g1.y+t1.y,
                            ge[6]*rstd*g1.z+t1.z, ge[7]*rstd*g1.w+t1.w);
    float4* op = reinterpret_cast<float4*>(out + (size_t)t * Dd);
    op[lane] = o0;
    op[lane + 32] = o1;
}

// -----------------------------------------------------------------------------
extern "C" void kernel_launch(void* const* d_in, const int* in_sizes, int n_in,
                              void* d_out, int out_size) {
    const float* x        = (const float*)d_in[0];
    const float* vn       = (const float*)d_in[2];
    const float* gat_W    = (const float*)d_in[3];
    const float* att_src  = (const float*)d_in[4];
    const float* att_dst  = (const float*)d_in[5];
    const float* gat_bias = (const float*)d_in[6];
    const float* gcn_W    = (const float*)d_in[7];
    const float* gcn_bias = (const float*)d_in[8];
    const float* n1g      = (const float*)d_in[9];
    const float* n1b      = (const float*)d_in[10];
    const float* n2g      = (const float*)d_in[11];
    const float* n2b      = (const float*)d_in[12];
    float* out = (float*)d_out;

    const int SMEM_BYTES = NSTAGE * STAGE_BYTES;   // 128 KB
    cudaFuncSetAttribute(k_mma_gemm, cudaFuncAttributeMaxDynamicSharedMemorySize, SMEM_BYTES);

    __nv_bfloat16 *pAhi, *pAlo, *pWmHi, *pWmLo, *pB2hi, *pB2lo, *pG1hi, *pG1lo;
    float *pHM, *pXW;
    cudaGetSymbolAddress((void**)&pAhi,  d_Ahi);
    cudaGetSymbolAddress((void**)&pAlo,  d_Alo);
    cudaGetSymbolAddress((void**)&pWmHi, d_WmHi);
    cudaGetSymbolAddress((void**)&pWmLo, d_WmLo);
    cudaGetSymbolAddress((void**)&pB2hi, d_B2hi);
    cudaGetSymbolAddress((void**)&pB2lo, d_B2lo);
    cudaGetSymbolAddress((void**)&pG1hi, d_G1hi);
    cudaGetSymbolAddress((void**)&pG1lo, d_G1lo);
    cudaGetSymbolAddress((void**)&pHM,   d_hmean);
    cudaGetSymbolAddress((void**)&pXW,   d_xw);

    k_prep<<<1024, 256>>>(gat_W, att_src, att_dst, gcn_W);
    k_build<<<Tt / 8, 256>>>(x, vn);

    k_mma_gemm<<<dim3(2, TP / 128), 256, SMEM_BYTES>>>(pAhi, pAlo, pWmHi, pWmLo, pHM);

    k_vwagg<<<Bb * NCHUNK, 256>>>(vn);
    k_yv<<<Bb * Hh, 256>>>(vn);
    k_norm1<<<Tt / 8, 256>>>(gat_bias, n1g, n1b);

    k_mma_gemm<<<dim3(2, TP / 128), 256, SMEM_BYTES>>>(pG1hi, pG1lo, pB2hi, pB2lo, pXW);

    k_final<<<BN / 8, 256>>>(gcn_bias, n2g, n2b, out);
}

// round 15
// speedup vs baseline: 1.0180x; 1.0180x over previous
#include <cuda_runtime.h>
#include <cuda_bf16.h>
#include <math.h>
#include <stdint.h>

#define Bb 32
#define Nn 512
#define Vv 5
#define Dd 256
#define Hh 4
#define BN (Bb*Nn)            // 16384 real nodes
#define Tt (BN + Bb*Vv)       // 16544 total nodes
#define TP 16640              // padded to 130*128 rows
#define Kk 256
#define NCHUNK 16

// ---------------- scratch ----------------------------------------------------
__device__ __nv_bfloat16 d_Ahi[(size_t)TP*Kk];
__device__ __nv_bfloat16 d_Alo[(size_t)TP*Kk];
__device__ __nv_bfloat16 d_WmHi[Dd*Kk];
__device__ __nv_bfloat16 d_WmLo[Dd*Kk];
__device__ __nv_bfloat16 d_B2hi[Dd*Kk];
__device__ __nv_bfloat16 d_B2lo[Dd*Kk];
__device__ float d_gatWt[1024*256];            // gat_W transposed [hc][k] fp32
__device__ float d_wsrc[Kk*Hh];
__device__ float d_wdst[Kk*Hh];
__device__ float d_hmean[(size_t)TP*Dd];
__device__ float d_asrc[Hh*Tt];                // [head][t]
__device__ float d_adst[Hh*Tt];
__device__ float d_w[128*Vv*520];              // softmax weights [bh*5+v][513]
__device__ float d_ypart[NCHUNK*Bb*20*Dd];
__device__ float d_gvirtH[Bb*Vv*Hh*Dd];
__device__ __nv_bfloat16 d_G1hi[(size_t)TP*Kk];
__device__ __nv_bfloat16 d_G1lo[(size_t)TP*Kk];
__device__ float d_xw[(size_t)TP*Dd];

// ---------------- helpers ----------------------------------------------------
__device__ __forceinline__ uint32_t smem_u32(const void* p) {
    uint32_t a;
    asm("{ .reg .u64 t; cvta.to.shared.u64 t, %1; cvt.u32.u64 %0, t; }"
        : "=r"(a) : "l"(p));
    return a;
}
__device__ __forceinline__ uint32_t sw64(uint32_t off) { return off ^ ((off >> 3) & 0x30); }

__device__ __forceinline__ void ldmx4(uint32_t* r, uint32_t addr) {
    asm volatile("ldmatrix.sync.aligned.m8n8.x4.shared.b16 {%0,%1,%2,%3}, [%4];"
                 : "=r"(r[0]), "=r"(r[1]), "=r"(r[2]), "=r"(r[3]) : "r"(addr));
}
__device__ __forceinline__ void mma16816(float* d, const uint32_t* a, uint32_t b0, uint32_t b1) {
    asm volatile(
        "mma.sync.aligned.m16n8k16.row.col.f32.bf16.bf16.f32 "
        "{%0,%1,%2,%3}, {%4,%5,%6,%7}, {%8,%9}, {%0,%1,%2,%3};"
        : "+f"(d[0]), "+f"(d[1]), "+f"(d[2]), "+f"(d[3])
        : "r"(a[0]), "r"(a[1]), "r"(a[2]), "r"(a[3]), "r"(b0), "r"(b1));
}
__device__ __forceinline__ void cp16(uint32_t smem_addr, const void* gptr) {
    asm volatile("cp.async.cg.shared.global [%0], [%1], 16;"
                 :: "r"(smem_addr), "l"(gptr));
}
__device__ __forceinline__ void cp_commit() {
    asm volatile("cp.async.commit_group;" ::: "memory");
}
__device__ __forceinline__ void cp_wait2() {
    asm volatile("cp.async.wait_group 2;" ::: "memory");
}
__device__ __forceinline__ void split_bf16(float v, __nv_bfloat16& hi, __nv_bfloat16& lo) {
    hi = __float2bfloat16(v);
    lo = __float2bfloat16(v - __bfloat162float(hi));
}
__device__ __forceinline__ uint32_t pack2(__nv_bfloat16 a, __nv_bfloat16 b) {
    return (uint32_t)__bfloat16_as_ushort(a) | ((uint32_t)__bfloat16_as_ushort(b) << 16);
}
__device__ __forceinline__ float warp_sum(float s) {
#pragma unroll
    for (int o = 16; o; o >>= 1) s += __shfl_xor_sync(0xffffffffu, s, o);
    return s;
}
__device__ __forceinline__ float lrelu(float x) { return x > 0.f ? x : 0.2f * x; }

// ---------------- fused prep (incl. gat_W transpose) -------------------------
__global__ void k_prep(const float* __restrict__ gat_W,
                       const float* __restrict__ att_src, const float* __restrict__ att_dst,
                       const float* __restrict__ gcn_W) {
    int bid = blockIdx.x;
    int tid = threadIdx.x;
    if (bid < 256) {
        int gw = bid * 8 + (tid >> 5);
        int lane = tid & 31;
        int k = gw >> 3;
        int h = (gw >> 1) & 3;
        bool is_dst = gw & 1;
        const float* wp = gat_W + (size_t)k * 1024 + h * 256;
        const float* ap = (is_dst ? att_dst : att_src) + h * 256;
        float s = 0.f;
#pragma unroll
        for (int j = 0; j < 8; j++) s += wp[lane + 32 * j] * ap[lane + 32 * j];
        s = warp_sum(s);
        if (lane == 0) {
            if (is_dst) d_wdst[k * 4 + h] = s;
            else        d_wsrc[k * 4 + h] = s;
        }
    } else if (bid < 512) {
        int n = bid - 256;
        int k = tid;
        const float* p = gat_W + (size_t)k * 1024 + n;
        float v = 0.25f * (p[0] + p[256] + p[512] + p[768]);
        __nv_bfloat16 hi, lo;
        split_bf16(v, hi, lo);
        d_WmHi[n * 256 + k] = hi;
        d_WmLo[n * 256 + k] = lo;
    } else if (bid < 768) {
        int idx = (bid - 512) * 256 + tid;
        int n = idx >> 8;
        int k = idx & 255;
        float v = gcn_W[k * 256 + n];
        __nv_bfloat16 hi, lo;
        split_bf16(v, hi, lo);
        d_B2hi[idx] = hi;
        d_B2lo[idx] = lo;
    } else {
        __shared__ float tile[32][33];
        int tix = bid - 768;
        int kt = tix & 7;
        int ct = tix >> 3;
        int row = tid >> 3;
        int col4 = (tid & 7) * 4;
#pragma unroll
        for (int j = 0; j < 4; j++)
            tile[row][col4 + j] = gat_W[(size_t)(kt * 32 + row) * 1024 + ct * 32 + col4 + j];
        __syncthreads();
#pragma unroll
        for (int j = 0; j < 4; j++)
            d_gatWt[(size_t)(ct * 32 + row) * 256 + kt * 32 + col4 + j] = tile[col4 + j][row];
    }
}

// ---------------- build: warp-per-node, vectorized, fused scores --------------
__global__ void __launch_bounds__(256) k_build(const float* __restrict__ x,
                                               const float* __restrict__ vn) {
    __shared__ float ws[8][256];
    int tid = threadIdx.x;
#pragma unroll
    for (int i = 0; i < 8; i++) {
        int idx = tid + i * 256;
        int r = idx >> 8, k = idx & 255;
        ws[r][k] = (r < 4) ? d_wsrc[k * 4 + r] : d_wdst[k * 4 + (r & 3)];
    }
    __syncthreads();

    int w = tid >> 5, lane = tid & 31;
    int t = blockIdx.x * 8 + w;
    const float* src = (t < BN) ? (x + (size_t)t * Dd)
                                : (vn + (size_t)((t - BN) % Vv) * Dd);
    float4 f0 = *reinterpret_cast<const float4*>(src + 4 * lane);
    float4 f1 = *reinterpret_cast<const float4*>(src + 128 + 4 * lane);

    __nv_bfloat16 h[8], l[8];
    split_bf16(f0.x, h[0], l[0]); split_bf16(f0.y, h[1], l[1]);
    split_bf16(f0.z, h[2], l[2]); split_bf16(f0.w, h[3], l[3]);
    split_bf16(f1.x, h[4], l[4]); split_bf16(f1.y, h[5], l[5]);
    split_bf16(f1.z, h[6], l[6]); split_bf16(f1.w, h[7], l[7]);
    uint2* Ahi2 = reinterpret_cast<uint2*>(d_Ahi + (size_t)t * Dd);
    uint2* Alo2 = reinterpret_cast<uint2*>(d_Alo + (size_t)t * Dd);
    Ahi2[lane]      = make_uint2(pack2(h[0], h[1]), pack2(h[2], h[3]));
    Ahi2[lane + 32] = make_uint2(pack2(h[4], h[5]), pack2(h[6], h[7]));
    Alo2[lane]      = make_uint2(pack2(l[0], l[1]), pack2(l[2], l[3]));
    Alo2[lane + 32] = make_uint2(pack2(l[4], l[5]), pack2(l[6], l[7]));

    float s[8];
#pragma unroll
    for (int r = 0; r < 8; r++) {
        const float4* wr = reinterpret_cast<const float4*>(ws[r]);
        float4 w0 = wr[lane], w1 = wr[lane + 32];
        s[r] = f0.x * w0.x + f0.y * w0.y + f0.z * w0.z + f0.w * w0.w
             + f1.x * w1.x + f1.y * w1.y + f1.z * w1.z + f1.w * w1.w;
    }
#pragma unroll
    for (int o = 16; o; o >>= 1)
#pragma unroll
        for (int r = 0; r < 8; r++) s[r] += __shfl_xor_sync(0xffffffffu, s[r], o);

    if (lane < 4)      d_asrc[lane * Tt + t] = s[lane];
    else if (lane < 8) d_adst[(lane - 4) * Tt + t] = s[lane];
}

// ---------------- pipelined mma.sync split-bf16 GEMM (proven config) ---------
#define NSTAGE 4
#define STAGE_BYTES 32768
#define OFF_AH 0
#define OFF_AL 8192
#define OFF_BH 16384
#define OFF_BL 24576

__global__ void __launch_bounds__(256) k_mma_gemm(
    const __nv_bfloat16* __restrict__ Ahi, const __nv_bfloat16* __restrict__ Alo,
    const __nv_bfloat16* __restrict__ Bhi, const __nv_bfloat16* __restrict__ Blo,
    float* __restrict__ C)
{
    extern __shared__ __align__(128) char smem[];
    const uint32_t sbase = smem_u32(smem);

    const int tid = threadIdx.x;
    const int wid = tid >> 5, lane = tid & 31;
    const int wm = (wid >> 2) * 64;
    const int wn = (wid & 3) * 32;
    const int mBase = blockIdx.y * 128;
    const int nBase = blockIdx.x * 128;

    const int lrow0 = tid >> 2;
    const int lc16  = tid & 3;
    const uint4* A4h = reinterpret_cast<const uint4*>(Ahi);
    const uint4* A4l = reinterpret_cast<const uint4*>(Alo);
    const uint4* B4h = reinterpret_cast<const uint4*>(Bhi);
    const uint4* B4l = reinterpret_cast<const uint4*>(Blo);

    float acc[4][4][4];
#pragma unroll
    for (int i = 0; i < 4; i++)
#pragma unroll
        for (int j = 0; j < 4; j++)
#pragma unroll
            for (int e = 0; e < 4; e++) acc[i][j][e] = 0.f;

    const uint32_t aRow = (uint32_t)((lane & 7) + (lane & 8));
    const uint32_t aColB = (lane & 16) ? 16u : 0u;
    const uint32_t bRow = (uint32_t)((lane & 7) + ((lane & 16) >> 1));
    const uint32_t bColB = (lane & 8) ? 16u : 0u;

    auto prefetch = [&](int kc) {
        uint32_t st = sbase + (kc & (NSTAGE - 1)) * STAGE_BYTES;
#pragma unroll
        for (int q = 0; q < 2; q++) {
            int row = lrow0 + q * 64;
            uint32_t sw = sw64((uint32_t)(row * 64 + lc16 * 16));
            int ga = (mBase + row) * 32 + kc * 4 + lc16;
            int gb = (nBase + row) * 32 + kc * 4 + lc16;
            cp16(st + OFF_AH + sw, A4h + ga);
            cp16(st + OFF_AL + sw, A4l + ga);
            cp16(st + OFF_BH + sw, B4h + gb);
            cp16(st + OFF_BL + sw, B4l + gb);
        }
    };

    prefetch(0); cp_commit();
    prefetch(1); cp_commit();
    prefetch(2); cp_commit();

    for (int kc = 0; kc < 8; kc++) {
        cp_wait2();
        __syncthreads();
        if (kc + 3 < 8) prefetch(kc + 3);
        cp_commit();

        uint32_t st = sbase + (kc & (NSTAGE - 1)) * STAGE_BYTES;
#pragma unroll
        for (int s = 0; s < 2; s++) {
            uint32_t bh[2][4], bl[2][4];
#pragma unroll
            for (int ng = 0; ng < 2; ng++) {
                uint32_t byteo = sw64((uint32_t)((wn + ng * 16 + bRow) * 64) + s * 32u + bColB);
                ldmx4(bh[ng], st + OFF_BH + byteo);
                ldmx4(bl[ng], st + OFF_BL + byteo);
            }
#pragma unroll
            for (int mt = 0; mt < 4; mt++) {
                uint32_t ah[4], al[4];
                uint32_t byteo = sw64((uint32_t)((wm + mt * 16 + aRow) * 64) + s * 32u + aColB);
                ldmx4(ah, st + OFF_AH + byteo);
                ldmx4(al, st + OFF_AL + byteo);
#pragma unroll
                for (int ng = 0; ng < 2; ng++) {
                    mma16816(acc[mt][ng * 2],     ah, bh[ng][0], bh[ng][1]);
                    mma16816(acc[mt][ng * 2 + 1], ah, bh[ng][2], bh[ng][3]);
                    mma16816(acc[mt][ng * 2],     ah, bl[ng][0], bl[ng][1]);
                    mma16816(acc[mt][ng * 2 + 1], ah, bl[ng][2], bl[ng][3]);
                    mma16816(acc[mt][ng * 2],     al, bh[ng][0], bh[ng][1]);
                    mma16816(acc[mt][ng * 2 + 1], al, bh[ng][2], bh[ng][3]);
                }
            }
        }
    }

    int mThr = mBase + wm + (lane >> 2);
    int nThr = nBase + wn + (lane & 3) * 2;
#pragma unroll
    for (int mt = 0; mt < 4; mt++)
#pragma unroll
        for (int nt = 0; nt < 4; nt++) {
            int r0 = mThr + mt * 16;
            int cc = nThr + nt * 8;
            float2 v0 = make_float2(acc[mt][nt][0], acc[mt][nt][1]);
            float2 v1 = make_float2(acc[mt][nt][2], acc[mt][nt][3]);
            *reinterpret_cast<float2*>(C + (size_t)r0 * 256 + cc) = v0;
            *reinterpret_cast<float2*>(C + (size_t)(r0 + 8) * 256 + cc) = v1;
        }
}

// ---------------- softmax weights: one block per (b,head,v) ------------------
__global__ void k_vw() {
    int g = blockIdx.x;                // bh*5 + v
    int bh = g / Vv, v = g % Vv;
    int b = bh >> 2, head = bh & 3;
    int tid = threadIdx.x;

    __shared__ float e_sh[Nn];
    __shared__ float red[256];

    int vt = BN + b * Vv + v;
    float adst = d_adst[head * Tt + vt];
    float aself = lrelu(d_asrc[head * Tt + vt] + adst);

    const float* ap = d_asrc + head * Tt + b * Nn;
    float a0 = lrelu(ap[tid] + adst);
    float a1 = lrelu(ap[tid + 256] + adst);

    float lm = fmaxf(fmaxf(a0, a1), aself);
    red[tid] = lm;
    __syncthreads();
    for (int s = 128; s > 0; s >>= 1) {
        if (tid < s) red[tid] = fmaxf(red[tid], red[tid + s]);
        __syncthreads();
    }
    float m = red[0];
    __syncthreads();

    float e0 = expf(a0 - m), e1 = expf(a1 - m);
    e_sh[tid] = e0;
    e_sh[tid + 256] = e1;
    float eS = expf(aself - m);
    float ls = e0 + e1 + ((tid == 0) ? eS : 0.f);
    red[tid] = ls;
    __syncthreads();
    for (int s = 128; s > 0; s >>= 1) {
        if (tid < s) red[tid] += red[tid + s];
        __syncthreads();
    }
    float inv = 1.f / red[0];

    float* wp = d_w + (size_t)g * 520;
    wp[tid] = e_sh[tid] * inv;
    wp[tid + 256] = e_sh[tid + 256] * inv;
    if (tid == 0) wp[512] = eS * inv;
}

// ---------------- weighted-x aggregation: 16 chunks of 32 --------------------
// x reconstructed from bf16 hi+lo (d_allf eliminated)
__global__ void k_yagg() {
    int b = blockIdx.x;
    int chunk = blockIdx.y;
    int c = threadIdx.x;

    __shared__ float w_sh[20][32];
    for (int idx = c; idx < 20 * 32; idx += 256) {
        int vh = idx >> 5, ii = idx & 31;
        int v = vh >> 2, h = vh & 3;
        w_sh[vh][ii] = d_w[(size_t)((b * 4 + h) * Vv + v) * 520 + chunk * 32 + ii];
    }
    __syncthreads();

    float acc[20];
#pragma unroll
    for (int j = 0; j < 20; j++) acc[j] = 0.f;

    size_t base = (size_t)(b * Nn + chunk * 32) * Dd + c;
    for (int ii = 0; ii < 32; ii++) {
        size_t idx = base + (size_t)ii * Dd;
        float xv = __bfloat162float(d_Ahi[idx]) + __bfloat162float(d_Alo[idx]);
#pragma unroll
        for (int j = 0; j < 20; j++) acc[j] += w_sh[j][ii] * xv;
    }
#pragma unroll
    for (int j = 0; j < 20; j++)
        d_ypart[(size_t)((chunk * Bb + b) * 20 + j) * Dd + c] = acc[j];
}

// ---------------- y-finalize + virtual GEMM (transposed weights) -------------
__global__ void __launch_bounds__(256) k_yv(const float* __restrict__ vn) {
    int g = blockIdx.x;
    int b = g >> 2, h = g & 3;
    int c = threadIdx.x;

    __shared__ float y[Vv][256];
#pragma unroll
    for (int v = 0; v < Vv; v++) {
        float s = 0.f;
        int vh = v * 4 + h;
#pragma unroll
        for (int chunk = 0; chunk < NCHUNK; chunk++)
            s += d_ypart[(size_t)((chunk * Bb + b) * 20 + vh) * Dd + c];
        s += d_w[(size_t)((b * 4 + h) * Vv + v) * 520 + 512] * vn[v * Dd + c];
        y[v][c] = s;
    }
    __syncthreads();

    float acc[Vv] = {0.f, 0.f, 0.f, 0.f, 0.f};
    const float4* wrow = reinterpret_cast<const float4*>(d_gatWt + (size_t)(h * 256 + c) * 256);
#pragma unroll 8
    for (int k4 = 0; k4 < 64; k4++) {
        float4 wv = wrow[k4];
        int k = k4 * 4;
#pragma unroll
        for (int v = 0; v < Vv; v++)
            acc[v] += y[v][k] * wv.x + y[v][k + 1] * wv.y
                    + y[v][k + 2] * wv.z + y[v][k + 3] * wv.w;
    }
#pragma unroll
    for (int v = 0; v < Vv; v++)
        d_gvirtH[(size_t)(((b * Vv + v) * 4) + h) * Dd + c] = acc[v];
}

// ---------------- gelu + layernorm (warp-per-node) ---------------------------
__device__ __forceinline__ float gelu_exact(float x) {
    return 0.5f * x * (1.f + erff(x * 0.70710678118654752f));
}

__global__ void __launch_bounds__(256) k_norm1(const float* __restrict__ gat_bias,
                                               const float* __restrict__ g,
                                               const float* __restrict__ bta) {
    int tid = threadIdx.x;
    int w = tid >> 5, lane = tid & 31;
    int t = blockIdx.x * 8 + w;

    float v[8];
    if (t < BN) {
        const float4* hp = reinterpret_cast<const float4*>(d_hmean + (size_t)t * Dd);
        float4 a = hp[lane], bq = hp[lane + 32];
        v[0]=a.x; v[1]=a.y; v[2]=a.z; v[3]=a.w;
        v[4]=bq.x; v[5]=bq.y; v[6]=bq.z; v[7]=bq.w;
    } else {
        size_t base = (size_t)(t - BN) * 4 * Dd;
        float4 s0 = make_float4(0,0,0,0), s1 = make_float4(0,0,0,0);
#pragma unroll
        for (int h = 0; h < 4; h++) {
            const float4* gp = reinterpret_cast<const float4*>(d_gvirtH + base + h * Dd);
            float4 a = gp[lane], bq = gp[lane + 32];
            s0.x += a.x; s0.y += a.y; s0.z += a.z; s0.w += a.w;
            s1.x += bq.x; s1.y += bq.y; s1.z += bq.z; s1.w += bq.w;
        }
        v[0]=0.25f*s0.x; v[1]=0.25f*s0.y; v[2]=0.25f*s0.z; v[3]=0.25f*s0.w;
        v[4]=0.25f*s1.x; v[5]=0.25f*s1.y; v[6]=0.25f*s1.z; v[7]=0.25f*s1.w;
    }
    const float4* bi = reinterpret_cast<const float4*>(gat_bias);
    float4 b0 = bi[lane], b1 = bi[lane + 32];
    v[0]+=b0.x; v[1]+=b0.y; v[2]+=b0.z; v[3]+=b0.w;
    v[4]+=b1.x; v[5]+=b1.y; v[6]+=b1.z; v[7]+=b1.w;

    float ge[8], s = 0.f;
#pragma unroll
    for (int i = 0; i < 8; i++) { ge[i] = gelu_exact(v[i]); s += ge[i]; }
    float mean = warp_sum(s) * (1.f / Dd);
    float sq = 0.f;
#pragma unroll
    for (int i = 0; i < 8; i++) { ge[i] -= mean; sq += ge[i] * ge[i]; }
    float rstd = rsqrtf(warp_sum(sq) * (1.f / Dd) + 1e-5f);

    const float4* gg = reinterpret_cast<const float4*>(g);
    const float4* gb = reinterpret_cast<const float4*>(bta);
    float4 g0 = gg[lane], g1 = gg[lane + 32];
    float4 t0 = gb[lane], t1 = gb[lane + 32];
    float o[8];
    o[0]=ge[0]*rstd*g0.x+t0.x; o[1]=ge[1]*rstd*g0.y+t0.y;
    o[2]=ge[2]*rstd*g0.z+t0.z; o[3]=ge[3]*rstd*g0.w+t0.w;
    o[4]=ge[4]*rstd*g1.x+t1.x; o[5]=ge[5]*rstd*g1.y+t1.y;
    o[6]=ge[6]*rstd*g1.z+t1.z; o[7]=ge[7]*rstd*g1.w+t1.w;

    __nv_bfloat16 h[8], l[8];
#pragma unroll
    for (int i = 0; i < 8; i++) split_bf16(o[i], h[i], l[i]);
    uint2* Ghi2 = reinterpret_cast<uint2*>(d_G1hi + (size_t)t * Dd);
    uint2* Glo2 = reinterpret_cast<uint2*>(d_G1lo + (size_t)t * Dd);
    Ghi2[lane]      = make_uint2(pack2(h[0], h[1]), pack2(h[2], h[3]));
    Ghi2[lane + 32] = make_uint2(pack2(h[4], h[5]), pack2(h[6], h[7]));
    Glo2[lane]      = make_uint2(pack2(l[0], l[1]), pack2(l[2], l[3]));
    Glo2[lane + 32] = make_uint2(pack2(l[4], l[5]), pack2(l[6], l[7]));
}

// final: warp per node, 8 nodes/block. vsum fused (virtual rows L2-resident).
__global__ void __launch_bounds__(256) k_final(const float* __restrict__ gcn_bias,
                                               const float* __restrict__ g,
                                               const float* __restrict__ bta,
                                               float* __restrict__ out) {
    int tid = threadIdx.x;
    int w = tid >> 5, lane = tid & 31;
    int t = blockIdx.x * 8 + w;
    int b = t >> 9;
    const float inv_sqrt6 = 0.40824829046386301637f;
    const float inv6 = 0.16666666666666666667f;

    float4 S0 = make_float4(0,0,0,0), S1 = make_float4(0,0,0,0);
#pragma unroll
    for (int v = 0; v < Vv; v++) {
        const float4* vp = reinterpret_cast<const float4*>(d_xw + (size_t)(BN + b * Vv + v) * Dd);
        float4 a = vp[lane], bq = vp[lane + 32];
        S0.x += a.x; S0.y += a.y; S0.z += a.z; S0.w += a.w;
        S1.x += bq.x; S1.y += bq.y; S1.z += bq.z; S1.w += bq.w;
    }

    const float4* xp = reinterpret_cast<const float4*>(d_xw + (size_t)t * Dd);
    const float4* bi = reinterpret_cast<const float4*>(gcn_bias);
    float4 x0 = xp[lane], x1 = xp[lane + 32];
    float4 b0 = bi[lane], b1 = bi[lane + 32];

    float v[8];
    v[0]=inv_sqrt6*S0.x+inv6*x0.x+b0.x; v[1]=inv_sqrt6*S0.y+inv6*x0.y+b0.y;
    v[2]=inv_sqrt6*S0.z+inv6*x0.z+b0.z; v[3]=inv_sqrt6*S0.w+inv6*x0.w+b0.w;
    v[4]=inv_sqrt6*S1.x+inv6*x1.x+b1.x; v[5]=inv_sqrt6*S1.y+inv6*x1.y+b1.y;
    v[6]=inv_sqrt6*S1.z+inv6*x1.z+b1.z; v[7]=inv_sqrt6*S1.w+inv6*x1.w+b1.w;

    float ge[8], s = 0.f;
#pragma unroll
    for (int i = 0; i < 8; i++) { ge[i] = gelu_exact(v[i]); s += ge[i]; }
    float mean = warp_sum(s) * (1.f / Dd);
    float sq = 0.f;
#pragma unroll
    for (int i = 0; i < 8; i++) { ge[i] -= mean; sq += ge[i] * ge[i]; }
    float rstd = rsqrtf(warp_sum(sq) * (1.f / Dd) + 1e-5f);

    const float4* gg = reinterpret_cast<const float4*>(g);
    const float4* gb = reinterpret_cast<const float4*>(bta);
    float4 g0 = gg[lane], g1 = gg[lane + 32];
    float4 t0 = gb[lane], t1 = gb[lane + 32];
    float4 o0 = make_float4(ge[0]*rstd*g0.x+t0.x, ge[1]*rstd*g0.y+t0.y,
                            ge[2]*rstd*g0.z+t0.z, ge[3]*rstd*g0.w+t0.w);
    float4 o1 = make_float4(ge[4]*rstd*g1.x+t1.x, ge[5]*rstd*g1.y+t1.y,
                            ge[6]*rstd*g1.z+t1.z, ge[7]*rstd*g1.w+t1.w);
    float4* op = reinterpret_cast<float4*>(out + (size_t)t * Dd);
    op[lane] = o0;
    op[lane + 32] = o1;
}

// -----------------------------------------------------------------------------
extern "C" void kernel_launch(void* const* d_in, const int* in_sizes, int n_in,
                              void* d_out, int out_size) {
    const float* x        = (const float*)d_in[0];
    const float* vn       = (const float*)d_in[2];
    const float* gat_W    = (const float*)d_in[3];
    const float* att_src  = (const float*)d_in[4];
    const float* att_dst  = (const float*)d_in[5];
    const float* gat_bias = (const float*)d_in[6];
    const float* gcn_W    = (const float*)d_in[7];
    const float* gcn_bias = (const float*)d_in[8];
    const float* n1g      = (const float*)d_in[9];
    const float* n1b      = (const float*)d_in[10];
    const float* n2g      = (const float*)d_in[11];
    const float* n2b      = (const float*)d_in[12];
    float* out = (float*)d_out;

    const int SMEM_BYTES = NSTAGE * STAGE_BYTES;   // 128 KB
    cudaFuncSetAttribute(k_mma_gemm, cudaFuncAttributeMaxDynamicSharedMemorySize, SMEM_BYTES);

    // side stream + events (created once, outside capture)
    static cudaStream_t s2 = nullptr;
    static cudaEvent_t evFork = nullptr, evJoin = nullptr;
    if (s2 == nullptr) {
        cudaStreamCreateWithFlags(&s2, cudaStreamNonBlocking);
        cudaEventCreateWithFlags(&evFork, cudaEventDisableTiming);
        cudaEventCreateWithFlags(&evJoin, cudaEventDisableTiming);
    }

    __nv_bfloat16 *pAhi, *pAlo, *pWmHi, *pWmLo, *pB2hi, *pB2lo, *pG1hi, *pG1lo;
    float *pHM, *pXW;
    cudaGetSymbolAddress((void**)&pAhi,  d_Ahi);
    cudaGetSymbolAddress((void**)&pAlo,  d_Alo);
    cudaGetSymbolAddress((void**)&pWmHi, d_WmHi);
    cudaGetSymbolAddress((void**)&pWmLo, d_WmLo);
    cudaGetSymbolAddress((void**)&pB2hi, d_B2hi);
    cudaGetSymbolAddress((void**)&pB2lo, d_B2lo);
    cudaGetSymbolAddress((void**)&pG1hi, d_G1hi);
    cudaGetSymbolAddress((void**)&pG1lo, d_G1lo);
    cudaGetSymbolAddress((void**)&pHM,   d_hmean);
    cudaGetSymbolAddress((void**)&pXW,   d_xw);

    k_prep<<<1024, 256>>>(gat_W, att_src, att_dst, gcn_W);
    k_build<<<Tt / 8, 256>>>(x, vn);

    // fork: vw/yagg/yv chain depends only on build (+prep), not GEMM1
    cudaEventRecord(evFork, 0);
    cudaStreamWaitEvent(s2, evFork, 0);

    k_mma_gemm<<<dim3(2, TP / 128), 256, SMEM_BYTES>>>(pAhi, pAlo, pWmHi, pWmLo, pHM);

    k_vw<<<128 * Vv, 256, 0, s2>>>();
    k_yagg<<<dim3(Bb, NCHUNK), 256, 0, s2>>>();
    k_yv<<<Bb * Hh, 256, 0, s2>>>(vn);

    // join: norm1 needs both hmean (GEMM1, stream 0) and gvirtH (yv, s2)
    cudaEventRecord(evJoin, s2);
    cudaStreamWaitEvent(0, evJoin, 0);

    k_norm1<<<Tt / 8, 256>>>(gat_bias, n1g, n1b);

    k_mma_gemm<<<dim3(2, TP / 128), 256, SMEM_BYTES>>>(pG1hi, pG1lo, pB2hi, pB2lo, pXW);

    k_final<<<BN / 8, 256>>>(gcn_bias, n2g, n2b, out);
}

// round 16
// speedup vs baseline: 1.0345x; 1.0162x over previous
#include <cuda_runtime.h>
#include <cuda_bf16.h>
#include <math.h>
#include <stdint.h>

#define Bb 32
#define Nn 512
#define Vv 5
#define Dd 256
#define Hh 4
#define BN (Bb*Nn)            // 16384 real nodes
#define Tt (BN + Bb*Vv)       // 16544 total nodes
#define TP 16640              // padded to 130*128 rows
#define Kk 256
#define NCHUNK 16

// ---------------- scratch ----------------------------------------------------
__device__ __nv_bfloat16 d_Ahi[(size_t)TP*Kk];
__device__ __nv_bfloat16 d_Alo[(size_t)TP*Kk];
__device__ __nv_bfloat16 d_WmHi[Dd*Kk];
__device__ __nv_bfloat16 d_WmLo[Dd*Kk];
__device__ __nv_bfloat16 d_B2hi[Dd*Kk];
__device__ __nv_bfloat16 d_B2lo[Dd*Kk];
__device__ float d_gatWt[1024*256];            // gat_W transposed [hc][k] fp32
__device__ float d_wsrc[Kk*Hh];
__device__ float d_wdst[Kk*Hh];
__device__ float d_hmean[(size_t)TP*Dd];
__device__ float d_asrc[Hh*Tt];                // [head][t]
__device__ float d_adst[Hh*Tt];
__device__ float d_w[128*Vv*520];              // softmax weights [bh*5+v][513]
__device__ float d_ypart[NCHUNK*Bb*20*Dd];
__device__ float d_gvirtH[Bb*Vv*Hh*Dd];
__device__ __nv_bfloat16 d_G1hi[(size_t)TP*Kk];
__device__ __nv_bfloat16 d_G1lo[(size_t)TP*Kk];
__device__ float d_xw[(size_t)TP*Dd];

// ---------------- helpers ----------------------------------------------------
__device__ __forceinline__ uint32_t smem_u32(const void* p) {
    uint32_t a;
    asm("{ .reg .u64 t; cvta.to.shared.u64 t, %1; cvt.u32.u64 %0, t; }"
        : "=r"(a) : "l"(p));
    return a;
}
__device__ __forceinline__ uint32_t sw64(uint32_t off) { return off ^ ((off >> 3) & 0x30); }

__device__ __forceinline__ void ldmx4(uint32_t* r, uint32_t addr) {
    asm volatile("ldmatrix.sync.aligned.m8n8.x4.shared.b16 {%0,%1,%2,%3}, [%4];"
                 : "=r"(r[0]), "=r"(r[1]), "=r"(r[2]), "=r"(r[3]) : "r"(addr));
}
__device__ __forceinline__ void mma16816(float* d, const uint32_t* a, uint32_t b0, uint32_t b1) {
    asm volatile(
        "mma.sync.aligned.m16n8k16.row.col.f32.bf16.bf16.f32 "
        "{%0,%1,%2,%3}, {%4,%5,%6,%7}, {%8,%9}, {%0,%1,%2,%3};"
        : "+f"(d[0]), "+f"(d[1]), "+f"(d[2]), "+f"(d[3])
        : "r"(a[0]), "r"(a[1]), "r"(a[2]), "r"(a[3]), "r"(b0), "r"(b1));
}
__device__ __forceinline__ void cp16(uint32_t smem_addr, const void* gptr) {
    asm volatile("cp.async.cg.shared.global [%0], [%1], 16;"
                 :: "r"(smem_addr), "l"(gptr));
}
__device__ __forceinline__ void cp_commit() {
    asm volatile("cp.async.commit_group;" ::: "memory");
}
__device__ __forceinline__ void cp_wait2() {
    asm volatile("cp.async.wait_group 2;" ::: "memory");
}
__device__ __forceinline__ void split_bf16(float v, __nv_bfloat16& hi, __nv_bfloat16& lo) {
    hi = __float2bfloat16(v);
    lo = __float2bfloat16(v - __bfloat162float(hi));
}
__device__ __forceinline__ uint32_t pack2(__nv_bfloat16 a, __nv_bfloat16 b) {
    return (uint32_t)__bfloat16_as_ushort(a) | ((uint32_t)__bfloat16_as_ushort(b) << 16);
}
__device__ __forceinline__ float warp_sum(float s) {
#pragma unroll
    for (int o = 16; o; o >>= 1) s += __shfl_xor_sync(0xffffffffu, s, o);
    return s;
}
__device__ __forceinline__ float lrelu(float x) { return x > 0.f ? x : 0.2f * x; }

// ---------------- fused prep (incl. gat_W transpose) -------------------------
__global__ void k_prep(const float* __restrict__ gat_W,
                       const float* __restrict__ att_src, const float* __restrict__ att_dst,
                       const float* __restrict__ gcn_W) {
    int bid = blockIdx.x;
    int tid = threadIdx.x;
    if (bid < 256) {
        int gw = bid * 8 + (tid >> 5);
        int lane = tid & 31;
        int k = gw >> 3;
        int h = (gw >> 1) & 3;
        bool is_dst = gw & 1;
        const float* wp = gat_W + (size_t)k * 1024 + h * 256;
        const float* ap = (is_dst ? att_dst : att_src) + h * 256;
        float s = 0.f;
#pragma unroll
        for (int j = 0; j < 8; j++) s += wp[lane + 32 * j] * ap[lane + 32 * j];
        s = warp_sum(s);
        if (lane == 0) {
            if (is_dst) d_wdst[k * 4 + h] = s;
            else        d_wsrc[k * 4 + h] = s;
        }
    } else if (bid < 512) {
        int n = bid - 256;
        int k = tid;
        const float* p = gat_W + (size_t)k * 1024 + n;
        float v = 0.25f * (p[0] + p[256] + p[512] + p[768]);
        __nv_bfloat16 hi, lo;
        split_bf16(v, hi, lo);
        d_WmHi[n * 256 + k] = hi;
        d_WmLo[n * 256 + k] = lo;
    } else if (bid < 768) {
        int idx = (bid - 512) * 256 + tid;
        int n = idx >> 8;
        int k = idx & 255;
        float v = gcn_W[k * 256 + n];
        __nv_bfloat16 hi, lo;
        split_bf16(v, hi, lo);
        d_B2hi[idx] = hi;
        d_B2lo[idx] = lo;
    } else {
        __shared__ float tile[32][33];
        int tix = bid - 768;
        int kt = tix & 7;
        int ct = tix >> 3;
        int row = tid >> 3;
        int col4 = (tid & 7) * 4;
#pragma unroll
        for (int j = 0; j < 4; j++)
            tile[row][col4 + j] = gat_W[(size_t)(kt * 32 + row) * 1024 + ct * 32 + col4 + j];
        __syncthreads();
#pragma unroll
        for (int j = 0; j < 4; j++)
            d_gatWt[(size_t)(ct * 32 + row) * 256 + kt * 32 + col4 + j] = tile[col4 + j][row];
    }
}

// ---------------- build: warp-per-node, vectorized, fused scores --------------
__global__ void __launch_bounds__(256) k_build(const float* __restrict__ x,
                                               const float* __restrict__ vn) {
    __shared__ float ws[8][256];
    int tid = threadIdx.x;
#pragma unroll
    for (int i = 0; i < 8; i++) {
        int idx = tid + i * 256;
        int r = idx >> 8, k = idx & 255;
        ws[r][k] = (r < 4) ? d_wsrc[k * 4 + r] : d_wdst[k * 4 + (r & 3)];
    }
    __syncthreads();

    int w = tid >> 5, lane = tid & 31;
    int t = blockIdx.x * 8 + w;
    const float* src = (t < BN) ? (x + (size_t)t * Dd)
                                : (vn + (size_t)((t - BN) % Vv) * Dd);
    float4 f0 = *reinterpret_cast<const float4*>(src + 4 * lane);
    float4 f1 = *reinterpret_cast<const float4*>(src + 128 + 4 * lane);

    __nv_bfloat16 h[8], l[8];
    split_bf16(f0.x, h[0], l[0]); split_bf16(f0.y, h[1], l[1]);
    split_bf16(f0.z, h[2], l[2]); split_bf16(f0.w, h[3], l[3]);
    split_bf16(f1.x, h[4], l[4]); split_bf16(f1.y, h[5], l[5]);
    split_bf16(f1.z, h[6], l[6]); split_bf16(f1.w, h[7], l[7]);
    uint2* Ahi2 = reinterpret_cast<uint2*>(d_Ahi + (size_t)t * Dd);
    uint2* Alo2 = reinterpret_cast<uint2*>(d_Alo + (size_t)t * Dd);
    Ahi2[lane]      = make_uint2(pack2(h[0], h[1]), pack2(h[2], h[3]));
    Ahi2[lane + 32] = make_uint2(pack2(h[4], h[5]), pack2(h[6], h[7]));
    Alo2[lane]      = make_uint2(pack2(l[0], l[1]), pack2(l[2], l[3]));
    Alo2[lane + 32] = make_uint2(pack2(l[4], l[5]), pack2(l[6], l[7]));

    float s[8];
#pragma unroll
    for (int r = 0; r < 8; r++) {
        const float4* wr = reinterpret_cast<const float4*>(ws[r]);
        float4 w0 = wr[lane], w1 = wr[lane + 32];
        s[r] = f0.x * w0.x + f0.y * w0.y + f0.z * w0.z + f0.w * w0.w
             + f1.x * w1.x + f1.y * w1.y + f1.z * w1.z + f1.w * w1.w;
    }
#pragma unroll
    for (int o = 16; o; o >>= 1)
#pragma unroll
        for (int r = 0; r < 8; r++) s[r] += __shfl_xor_sync(0xffffffffu, s[r], o);

    if (lane < 4)      d_asrc[lane * Tt + t] = s[lane];
    else if (lane < 8) d_adst[(lane - 4) * Tt + t] = s[lane];
}

// ---------------- single-wave persistent GEMM with A-reuse -------------------
// grid 130 (m-blocks); each CTA computes n=0 and n=1 for its 128-row m-strip.
// A (hi+lo, all 8 k-chunks) resident in 128KB of smem; B streams via 4-slot
// ring (64KB). 16 virtual chunks: vc<8 loads A+B(n=0), vc>=8 loads B(n=1) only.
#define ASLOT 16384            // per-kc A slot: hi 8KB + lo 8KB
#define BRING_OFF (8*ASLOT)    // 128 KB
#define BSLOT 16384            // per-ring B slot: hi 8KB + lo 8KB
#define GEMM_SMEM (BRING_OFF + 4*BSLOT)   // 192 KB

__global__ void __launch_bounds__(256) k_mma_gemm(
    const __nv_bfloat16* __restrict__ Ahi, const __nv_bfloat16* __restrict__ Alo,
    const __nv_bfloat16* __restrict__ Bhi, const __nv_bfloat16* __restrict__ Blo,
    float* __restrict__ C)
{
    extern __shared__ __align__(128) char smem[];
    const uint32_t sbase = smem_u32(smem);

    const int tid = threadIdx.x;
    const int wid = tid >> 5, lane = tid & 31;
    const int wm = (wid >> 2) * 64;
    const int wn = (wid & 3) * 32;
    const int mBase = blockIdx.x * 128;

    const int lrow0 = tid >> 2;
    const int lc16  = tid & 3;
    const uint4* A4h = reinterpret_cast<const uint4*>(Ahi);
    const uint4* A4l = reinterpret_cast<const uint4*>(Alo);
    const uint4* B4h = reinterpret_cast<const uint4*>(Bhi);
    const uint4* B4l = reinterpret_cast<const uint4*>(Blo);

    float acc[4][4][4];
#pragma unroll
    for (int i = 0; i < 4; i++)
#pragma unroll
        for (int j = 0; j < 4; j++)
#pragma unroll
            for (int e = 0; e < 4; e++) acc[i][j][e] = 0.f;

    const uint32_t aRow = (uint32_t)((lane & 7) + (lane & 8));
    const uint32_t aColB = (lane & 16) ? 16u : 0u;
    const uint32_t bRow = (uint32_t)((lane & 7) + ((lane & 16) >> 1));
    const uint32_t bColB = (lane & 8) ? 16u : 0u;

    auto prefetch = [&](int vc) {
        int kc = vc & 7;
        int n = vc >> 3;               // 0 or 1
        uint32_t aB = sbase + kc * ASLOT;
        uint32_t bB = sbase + BRING_OFF + (vc & 3) * BSLOT;
#pragma unroll
        for (int q = 0; q < 2; q++) {
            int row = lrow0 + q * 64;
            uint32_t sw = sw64((uint32_t)(row * 64 + lc16 * 16));
            if (vc < 8) {              // A load only during first n-phase
                int ga = (mBase + row) * 32 + kc * 4 + lc16;
                cp16(aB + sw, A4h + ga);
                cp16(aB + 8192 + sw, A4l + ga);
            }
            int gb = (n * 128 + row) * 32 + kc * 4 + lc16;
            cp16(bB + sw, B4h + gb);
            cp16(bB + 8192 + sw, B4l + gb);
        }
    };

    auto epilogue = [&](int nBase) {
        int mThr = mBase + wm + (lane >> 2);
        int nThr = nBase + wn + (lane & 3) * 2;
#pragma unroll
        for (int mt = 0; mt < 4; mt++)
#pragma unroll
            for (int nt = 0; nt < 4; nt++) {
                int r0 = mThr + mt * 16;
                int cc = nThr + nt * 8;
                float2 v0 = make_float2(acc[mt][nt][0], acc[mt][nt][1]);
                float2 v1 = make_float2(acc[mt][nt][2], acc[mt][nt][3]);
                *reinterpret_cast<float2*>(C + (size_t)r0 * 256 + cc) = v0;
                *reinterpret_cast<float2*>(C + (size_t)(r0 + 8) * 256 + cc) = v1;
                acc[mt][nt][0] = 0.f; acc[mt][nt][1] = 0.f;
                acc[mt][nt][2] = 0.f; acc[mt][nt][3] = 0.f;
            }
    };

    prefetch(0); cp_commit();
    prefetch(1); cp_commit();
    prefetch(2); cp_commit();

    for (int vc = 0; vc < 16; vc++) {
        cp_wait2();
        __syncthreads();
        if (vc + 3 < 16) prefetch(vc + 3);
        cp_commit();

        uint32_t aB = sbase + (vc & 7) * ASLOT;
        uint32_t bB = sbase + BRING_OFF + (vc & 3) * BSLOT;
#pragma unroll
        for (int s = 0; s < 2; s++) {
            uint32_t bh[2][4], bl[2][4];
#pragma unroll
            for (int ng = 0; ng < 2; ng++) {
                uint32_t byteo = sw64((uint32_t)((wn + ng * 16 + bRow) * 64) + s * 32u + bColB);
                ldmx4(bh[ng], bB + byteo);
                ldmx4(bl[ng], bB + 8192 + byteo);
            }
#pragma unroll
            for (int mt = 0; mt < 4; mt++) {
                uint32_t ah[4], al[4];
                uint32_t byteo = sw64((uint32_t)((wm + mt * 16 + aRow) * 64) + s * 32u + aColB);
                ldmx4(ah, aB + byteo);
                ldmx4(al, aB + 8192 + byteo);
#pragma unroll
                for (int ng = 0; ng < 2; ng++) {
                    mma16816(acc[mt][ng * 2],     ah, bh[ng][0], bh[ng][1]);
                    mma16816(acc[mt][ng * 2 + 1], ah, bh[ng][2], bh[ng][3]);
                    mma16816(acc[mt][ng * 2],     ah, bl[ng][0], bl[ng][1]);
                    mma16816(acc[mt][ng * 2 + 1], ah, bl[ng][2], bl[ng][3]);
                    mma16816(acc[mt][ng * 2],     al, bh[ng][0], bh[ng][1]);
                    mma16816(acc[mt][ng * 2 + 1], al, bh[ng][2], bh[ng][3]);
                }
            }
        }
        if (vc == 7)  epilogue(0);
        if (vc == 15) epilogue(128);
    }
}

// ---------------- softmax weights: one block per (b,head,v) ------------------
__global__ void k_vw() {
    int g = blockIdx.x;                // bh*5 + v
    int bh = g / Vv, v = g % Vv;
    int b = bh >> 2, head = bh & 3;
    int tid = threadIdx.x;

    __shared__ float e_sh[Nn];
    __shared__ float red[256];

    int vt = BN + b * Vv + v;
    float adst = d_adst[head * Tt + vt];
    float aself = lrelu(d_asrc[head * Tt + vt] + adst);

    const float* ap = d_asrc + head * Tt + b * Nn;
    float a0 = lrelu(ap[tid] + adst);
    float a1 = lrelu(ap[tid + 256] + adst);

    float lm = fmaxf(fmaxf(a0, a1), aself);
    red[tid] = lm;
    __syncthreads();
    for (int s = 128; s > 0; s >>= 1) {
        if (tid < s) red[tid] = fmaxf(red[tid], red[tid + s]);
        __syncthreads();
    }
    float m = red[0];
    __syncthreads();

    float e0 = expf(a0 - m), e1 = expf(a1 - m);
    e_sh[tid] = e0;
    e_sh[tid + 256] = e1;
    float eS = expf(aself - m);
    float ls = e0 + e1 + ((tid == 0) ? eS : 0.f);
    red[tid] = ls;
    __syncthreads();
    for (int s = 128; s > 0; s >>= 1) {
        if (tid < s) red[tid] += red[tid + s];
        __syncthreads();
    }
    float inv = 1.f / red[0];

    float* wp = d_w + (size_t)g * 520;
    wp[tid] = e_sh[tid] * inv;
    wp[tid + 256] = e_sh[tid + 256] * inv;
    if (tid == 0) wp[512] = eS * inv;
}

// ---------------- weighted-x aggregation: 16 chunks of 32 --------------------
__global__ void k_yagg() {
    int b = blockIdx.x;
    int chunk = blockIdx.y;
    int c = threadIdx.x;

    __shared__ float w_sh[20][32];
    for (int idx = c; idx < 20 * 32; idx += 256) {
        int vh = idx >> 5, ii = idx & 31;
        int v = vh >> 2, h = vh & 3;
        w_sh[vh][ii] = d_w[(size_t)((b * 4 + h) * Vv + v) * 520 + chunk * 32 + ii];
    }
    __syncthreads();

    float acc[20];
#pragma unroll
    for (int j = 0; j < 20; j++) acc[j] = 0.f;

    size_t base = (size_t)(b * Nn + chunk * 32) * Dd + c;
    for (int ii = 0; ii < 32; ii++) {
        size_t idx = base + (size_t)ii * Dd;
        float xv = __bfloat162float(d_Ahi[idx]) + __bfloat162float(d_Alo[idx]);
#pragma unroll
        for (int j = 0; j < 20; j++) acc[j] += w_sh[j][ii] * xv;
    }
#pragma unroll
    for (int j = 0; j < 20; j++)
        d_ypart[(size_t)((chunk * Bb + b) * 20 + j) * Dd + c] = acc[j];
}

// ---------------- y-finalize + virtual GEMM (transposed weights) -------------
__global__ void __launch_bounds__(256) k_yv(const float* __restrict__ vn) {
    int g = blockIdx.x;
    int b = g >> 2, h = g & 3;
    int c = threadIdx.x;

    __shared__ float y[Vv][256];
#pragma unroll
    for (int v = 0; v < Vv; v++) {
        float s = 0.f;
        int vh = v * 4 + h;
#pragma unroll
        for (int chunk = 0; chunk < NCHUNK; chunk++)
            s += d_ypart[(size_t)((chunk * Bb + b) * 20 + vh) * Dd + c];
        s += d_w[(size_t)((b * 4 + h) * Vv + v) * 520 + 512] * vn[v * Dd + c];
        y[v][c] = s;
    }
    __syncthreads();

    float acc[Vv] = {0.f, 0.f, 0.f, 0.f, 0.f};
    const float4* wrow = reinterpret_cast<const float4*>(d_gatWt + (size_t)(h * 256 + c) * 256);
#pragma unroll 8
    for (int k4 = 0; k4 < 64; k4++) {
        float4 wv = wrow[k4];
        int k = k4 * 4;
#pragma unroll
        for (int v = 0; v < Vv; v++)
            acc[v] += y[v][k] * wv.x + y[v][k + 1] * wv.y
                    + y[v][k + 2] * wv.z + y[v][k + 3] * wv.w;
    }
#pragma unroll
    for (int v = 0; v < Vv; v++)
        d_gvirtH[(size_t)(((b * Vv + v) * 4) + h) * Dd + c] = acc[v];
}

// ---------------- gelu + layernorm (warp-per-node) ---------------------------
__device__ __forceinline__ float gelu_exact(float x) {
    return 0.5f * x * (1.f + erff(x * 0.70710678118654752f));
}

__global__ void __launch_bounds__(256) k_norm1(const float* __restrict__ gat_bias,
                                               const float* __restrict__ g,
                                               const float* __restrict__ bta) {
    int tid = threadIdx.x;
    int w = tid >> 5, lane = tid & 31;
    int t = blockIdx.x * 8 + w;

    float v[8];
    if (t < BN) {
        const float4* hp = reinterpret_cast<const float4*>(d_hmean + (size_t)t * Dd);
        float4 a = hp[lane], bq = hp[lane + 32];
        v[0]=a.x; v[1]=a.y; v[2]=a.z; v[3]=a.w;
        v[4]=bq.x; v[5]=bq.y; v[6]=bq.z; v[7]=bq.w;
    } else {
        size_t base = (size_t)(t - BN) * 4 * Dd;
        float4 s0 = make_float4(0,0,0,0), s1 = make_float4(0,0,0,0);
#pragma unroll
        for (int h = 0; h < 4; h++) {
            const float4* gp = reinterpret_cast<const float4*>(d_gvirtH + base + h * Dd);
            float4 a = gp[lane], bq = gp[lane + 32];
            s0.x += a.x; s0.y += a.y; s0.z += a.z; s0.w += a.w;
            s1.x += bq.x; s1.y += bq.y; s1.z += bq.z; s1.w += bq.w;
        }
        v[0]=0.25f*s0.x; v[1]=0.25f*s0.y; v[2]=0.25f*s0.z; v[3]=0.25f*s0.w;
        v[4]=0.25f*s1.x; v[5]=0.25f*s1.y; v[6]=0.25f*s1.z; v[7]=0.25f*s1.w;
    }
    const float4* bi = reinterpret_cast<const float4*>(gat_bias);
    float4 b0 = bi[lane], b1 = bi[lane + 32];
    v[0]+=b0.x; v[1]+=b0.y; v[2]+=b0.z; v[3]+=b0.w;
    v[4]+=b1.x; v[5]+=b1.y; v[6]+=b1.z; v[7]+=b1.w;

    float ge[8], s = 0.f;
#pragma unroll
    for (int i = 0; i < 8; i++) { ge[i] = gelu_exact(v[i]); s += ge[i]; }
    float mean = warp_sum(s) * (1.f / Dd);
    float sq = 0.f;
#pragma unroll
    for (int i = 0; i < 8; i++) { ge[i] -= mean; sq += ge[i] * ge[i]; }
    float rstd = rsqrtf(warp_sum(sq) * (1.f / Dd) + 1e-5f);

    const float4* gg = reinterpret_cast<const float4*>(g);
    const float4* gb = reinterpret_cast<const float4*>(bta);
    float4 g0 = gg[lane], g1 = gg[lane + 32];
    float4 t0 = gb[lane], t1 = gb[lane + 32];
    float o[8];
    o[0]=ge[0]*rstd*g0.x+t0.x; o[1]=ge[1]*rstd*g0.y+t0.y;
    o[2]=ge[2]*rstd*g0.z+t0.z; o[3]=ge[3]*rstd*g0.w+t0.w;
    o[4]=ge[4]*rstd*g1.x+t1.x; o[5]=ge[5]*rstd*g1.y+t1.y;
    o[6]=ge[6]*rstd*g1.z+t1.z; o[7]=ge[7]*rstd*g1.w+t1.w;

    __nv_bfloat16 h[8], l[8];
#pragma unroll
    for (int i = 0; i < 8; i++) split_bf16(o[i], h[i], l[i]);
    uint2* Ghi2 = reinterpret_cast<uint2*>(d_G1hi + (size_t)t * Dd);
    uint2* Glo2 = reinterpret_cast<uint2*>(d_G1lo + (size_t)t * Dd);
    Ghi2[lane]      = make_uint2(pack2(h[0], h[1]), pack2(h[2], h[3]));
    Ghi2[lane + 32] = make_uint2(pack2(h[4], h[5]), pack2(h[6], h[7]));
    Glo2[lane]      = make_uint2(pack2(l[0], l[1]), pack2(l[2], l[3]));
    Glo2[lane + 32] = make_uint2(pack2(l[4], l[5]), pack2(l[6], l[7]));
}

// final: warp per node, 8 nodes/block. vsum fused (virtual rows L2-resident).
__global__ void __launch_bounds__(256) k_final(const float* __restrict__ gcn_bias,
                                               const float* __restrict__ g,
                                               const float* __restrict__ bta,
                                               float* __restrict__ out) {
    int tid = threadIdx.x;
    int w = tid >> 5, lane = tid & 31;
    int t = blockIdx.x * 8 + w;
    int b = t >> 9;
    const float inv_sqrt6 = 0.40824829046386301637f;
    const float inv6 = 0.16666666666666666667f;

    float4 S0 = make_float4(0,0,0,0), S1 = make_float4(0,0,0,0);
#pragma unroll
    for (int v = 0; v < Vv; v++) {
        const float4* vp = reinterpret_cast<const float4*>(d_xw + (size_t)(BN + b * Vv + v) * Dd);
        float4 a = vp[lane], bq = vp[lane + 32];
        S0.x += a.x; S0.y += a.y; S0.z += a.z; S0.w += a.w;
        S1.x += bq.x; S1.y += bq.y; S1.z += bq.z; S1.w += bq.w;
    }

    const float4* xp = reinterpret_cast<const float4*>(d_xw + (size_t)t * Dd);
    const float4* bi = reinterpret_cast<const float4*>(gcn_bias);
    float4 x0 = xp[lane], x1 = xp[lane + 32];
    float4 b0 = bi[lane], b1 = bi[lane + 32];

    float v[8];
    v[0]=inv_sqrt6*S0.x+inv6*x0.x+b0.x; v[1]=inv_sqrt6*S0.y+inv6*x0.y+b0.y;
    v[2]=inv_sqrt6*S0.z+inv6*x0.z+b0.z; v[3]=inv_sqrt6*S0.w+inv6*x0.w+b0.w;
    v[4]=inv_sqrt6*S1.x+inv6*x1.x+b1.x; v[5]=inv_sqrt6*S1.y+inv6*x1.y+b1.y;
    v[6]=inv_sqrt6*S1.z+inv6*x1.z+b1.z; v[7]=inv_sqrt6*S1.w+inv6*x1.w+b1.w;

    float ge[8], s = 0.f;
#pragma unroll
    for (int i = 0; i < 8; i++) { ge[i] = gelu_exact(v[i]); s += ge[i]; }
    float mean = warp_sum(s) * (1.f / Dd);
    float sq = 0.f;
#pragma unroll
    for (int i = 0; i < 8; i++) { ge[i] -= mean; sq += ge[i] * ge[i]; }
    float rstd = rsqrtf(warp_sum(sq) * (1.f / Dd) + 1e-5f);

    const float4* gg = reinterpret_cast<const float4*>(g);
    const float4* gb = reinterpret_cast<const float4*>(bta);
    float4 g0 = gg[lane], g1 = gg[lane + 32];
    float4 t0 = gb[lane], t1 = gb[lane + 32];
    float4 o0 = make_float4(ge[0]*rstd*g0.x+t0.x, ge[1]*rstd*g0.y+t0.y,
                            ge[2]*rstd*g0.z+t0.z, ge[3]*rstd*g0.w+t0.w);
    float4 o1 = make_float4(ge[4]*rstd*g1.x+t1.x, ge[5]*rstd*g1.y+t1.y,
                            ge[6]*rstd*g1.z+t1.z, ge[7]*rstd*g1.w+t1.w);
    float4* op = reinterpret_cast<float4*>(out + (size_t)t * Dd);
    op[lane] = o0;
    op[lane + 32] = o1;
}

// -----------------------------------------------------------------------------
extern "C" void kernel_launch(void* const* d_in, const int* in_sizes, int n_in,
                              void* d_out, int out_size) {
    const float* x        = (const float*)d_in[0];
    const float* vn       = (const float*)d_in[2];
    const float* gat_W    = (const float*)d_in[3];
    const float* att_src  = (const float*)d_in[4];
    const float* att_dst  = (const float*)d_in[5];
    const float* gat_bias = (const float*)d_in[6];
    const float* gcn_W    = (const float*)d_in[7];
    const float* gcn_bias = (const float*)d_in[8];
    const float* n1g      = (const float*)d_in[9];
    const float* n1b      = (const float*)d_in[10];
    const float* n2g      = (const float*)d_in[11];
    const float* n2b      = (const float*)d_in[12];
    float* out = (float*)d_out;

    cudaFuncSetAttribute(k_mma_gemm, cudaFuncAttributeMaxDynamicSharedMemorySize, GEMM_SMEM);

    // side stream + events (created once, outside capture)
    static cudaStream_t s2 = nullptr;
    static cudaEvent_t evFork = nullptr, evJoin = nullptr;
    if (s2 == nullptr) {
        cudaStreamCreateWithFlags(&s2, cudaStreamNonBlocking);
        cudaEventCreateWithFlags(&evFork, cudaEventDisableTiming);
        cudaEventCreateWithFlags(&evJoin, cudaEventDisableTiming);
    }

    __nv_bfloat16 *pAhi, *pAlo, *pWmHi, *pWmLo, *pB2hi, *pB2lo, *pG1hi, *pG1lo;
    float *pHM, *pXW;
    cudaGetSymbolAddress((void**)&pAhi,  d_Ahi);
    cudaGetSymbolAddress((void**)&pAlo,  d_Alo);
    cudaGetSymbolAddress((void**)&pWmHi, d_WmHi);
    cudaGetSymbolAddress((void**)&pWmLo, d_WmLo);
    cudaGetSymbolAddress((void**)&pB2hi, d_B2hi);
    cudaGetSymbolAddress((void**)&pB2lo, d_B2lo);
    cudaGetSymbolAddress((void**)&pG1hi, d_G1hi);
    cudaGetSymbolAddress((void**)&pG1lo, d_G1lo);
    cudaGetSymbolAddress((void**)&pHM,   d_hmean);
    cudaGetSymbolAddress((void**)&pXW,   d_xw);

    k_prep<<<1024, 256>>>(gat_W, att_src, att_dst, gcn_W);
    k_build<<<Tt / 8, 256>>>(x, vn);

    // fork: vw/yagg/yv chain depends only on build (+prep), not GEMM1
    cudaEventRecord(evFork, 0);
    cudaStreamWaitEvent(s2, evFork, 0);

    k_mma_gemm<<<TP / 128, 256, GEMM_SMEM>>>(pAhi, pAlo, pWmHi, pWmLo, pHM);

    k_vw<<<128 * Vv, 256, 0, s2>>>();
    k_yagg<<<dim3(Bb, NCHUNK), 256, 0, s2>>>();
    k_yv<<<Bb * Hh, 256, 0, s2>>>(vn);

    // join: norm1 needs both hmean (GEMM1, stream 0) and gvirtH (yv, s2)
    cudaEventRecord(evJoin, s2);
    cudaStreamWaitEvent(0, evJoin, 0);

    k_norm1<<<Tt / 8, 256>>>(gat_bias, n1g, n1b);

    k_mma_gemm<<<TP / 128, 256, GEMM_SMEM>>>(pG1hi, pG1lo, pB2hi, pB2lo, pXW);

    k_final<<<BN / 8, 256>>>(gcn_bias, n2g, n2b, out);
}